// round 7
// baseline (speedup 1.0000x reference)
#include <cuda_runtime.h>
#include <cuda_bf16.h>
#include <cstdint>

// out[i,j] = dot(z1[i], z2[j]) if batch[i]==batch[j] && cls[i]==cls[j]
//            && !(24<=cls[i]<=26) && i!=j, else 0.
//
// Single fused kernel. Each CTA owns 8 output rows:
//   - zero-fill its rows via cp.async.bulk SMEM->GMEM (TMA store path: one
//     instruction per 16KB => fill is not issue-limited like STG loops)
//   - concurrently compute the rows' sparse dot products into SMEM staging
//   - wait for the bulk stores, then scatter the staged values.
// Values only ever target this CTA's own rows => per-CTA ordering suffices.

#define ROWS_PER_CTA 8
#define CHUNK 16384              // bulk-store chunk bytes (SMEM zero buffer)
#define CAP   64                 // staged matches per row (avg ~9.5)

__device__ __forceinline__ int lower_bound_dev(const int* __restrict__ a, int n, int v) {
    int lo = 0, hi = n;
    while (lo < hi) { int m = (lo + hi) >> 1; if (a[m] < v) lo = m + 1; else hi = m; }
    return lo;
}
__device__ __forceinline__ int upper_bound_dev(const int* __restrict__ a, int n, int v) {
    int lo = 0, hi = n;
    while (lo < hi) { int m = (lo + hi) >> 1; if (a[m] <= v) lo = m + 1; else hi = m; }
    return lo;
}
__device__ __forceinline__ float warp_reduce_add(float d) {
    d += __shfl_xor_sync(0xffffffffu, d, 16);
    d += __shfl_xor_sync(0xffffffffu, d, 8);
    d += __shfl_xor_sync(0xffffffffu, d, 4);
    d += __shfl_xor_sync(0xffffffffu, d, 2);
    d += __shfl_xor_sync(0xffffffffu, d, 1);
    return d;
}
__device__ __forceinline__ void bulk_store_g_s(void* gmem, uint32_t smem, uint32_t bytes) {
    asm volatile("cp.async.bulk.global.shared::cta.bulk_group [%0], [%1], %2;"
                 :: "l"(gmem), "r"(smem), "r"(bytes) : "memory");
}

__global__ void __launch_bounds__(128)
fused_tma_fill_d128(const float* __restrict__ z1,
                    const float* __restrict__ z2,
                    const int*  __restrict__ cls,
                    const int*  __restrict__ batch,
                    float* __restrict__ out,
                    int N, int chunksPerRow)
{
    __shared__ float zbuf[CHUNK / 4];                 // 16 KB of zeros
    __shared__ int   scol[ROWS_PER_CTA][CAP];
    __shared__ float sval[ROWS_PER_CTA][CAP];
    __shared__ int   scnt[ROWS_PER_CTA];
    __shared__ int   sover[ROWS_PER_CTA];

    const int tid  = threadIdx.x;
    const int lane = tid & 31;
    const int w    = tid >> 5;                        // 4 warps
    const int row0 = blockIdx.x * ROWS_PER_CTA;

    // --- zero the bulk-store source buffer ---
    {
        float4* z4 = reinterpret_cast<float4*>(zbuf);
        const float4 z = make_float4(0.f, 0.f, 0.f, 0.f);
        #pragma unroll
        for (int i = tid; i < CHUNK / 16; i += 128) z4[i] = z;
        if (tid < ROWS_PER_CTA) { scnt[tid] = 0; sover[tid] = 0; }
    }
    asm volatile("fence.proxy.async.shared::cta;" ::: "memory");
    __syncthreads();

    // --- issue the zero-fill bulk stores for this CTA's rows ---
    if (tid == 0) {
        const uint32_t saddr = (uint32_t)__cvta_generic_to_shared(zbuf);
        for (int r = 0; r < ROWS_PER_CTA; r++) {
            char* dst = reinterpret_cast<char*>(out + (size_t)(row0 + r) * (size_t)N);
            for (int c = 0; c < chunksPerRow; c++)
                bulk_store_g_s(dst + (size_t)c * CHUNK, saddr, CHUNK);
        }
        asm volatile("cp.async.bulk.commit_group;" ::: "memory");
    }

    // --- sparse compute into SMEM staging (overlaps the fill flight) ---
    // warp w handles rows row0+2w, row0+2w+1
    for (int rr = w * 2; rr < w * 2 + 2; rr++) {
        const int row = row0 + rr;
        const int ci = cls[row];
        int k = 0;
        if (!(ci >= 24 && ci <= 26)) {
            const int bi = batch[row];
            const int lo = lower_bound_dev(batch, N, bi);
            const int hi = upper_bound_dev(batch, N, bi);
            const float4 a = reinterpret_cast<const float4*>(z1 + (size_t)row * 128)[lane];
            const float4 zv = make_float4(0.f, 0.f, 0.f, 0.f);

            for (int jb = lo; jb < hi; jb += 32) {
                const int j = jb + lane;
                const bool p = (j < hi) && (j != row) && (cls[j] == ci);
                unsigned m = __ballot_sync(0xffffffffu, p);
                while (m) {
                    int jj0 = jb + __ffs(m) - 1; m &= m - 1;
                    int jj1 = -1, jj2 = -1, jj3 = -1;
                    if (m) { jj1 = jb + __ffs(m) - 1; m &= m - 1; }
                    if (m) { jj2 = jb + __ffs(m) - 1; m &= m - 1; }
                    if (m) { jj3 = jb + __ffs(m) - 1; m &= m - 1; }

                    float4 v0 = reinterpret_cast<const float4*>(z2 + (size_t)jj0 * 128)[lane];
                    float4 v1 = (jj1 >= 0) ? reinterpret_cast<const float4*>(z2 + (size_t)jj1 * 128)[lane] : zv;
                    float4 v2 = (jj2 >= 0) ? reinterpret_cast<const float4*>(z2 + (size_t)jj2 * 128)[lane] : zv;
                    float4 v3 = (jj3 >= 0) ? reinterpret_cast<const float4*>(z2 + (size_t)jj3 * 128)[lane] : zv;

                    float d0 = a.x * v0.x + a.y * v0.y + a.z * v0.z + a.w * v0.w;
                    float d1 = a.x * v1.x + a.y * v1.y + a.z * v1.z + a.w * v1.w;
                    float d2 = a.x * v2.x + a.y * v2.y + a.z * v2.z + a.w * v2.w;
                    float d3 = a.x * v3.x + a.y * v3.y + a.z * v3.z + a.w * v3.w;

                    d0 = warp_reduce_add(d0);
                    d1 = warp_reduce_add(d1);
                    d2 = warp_reduce_add(d2);
                    d3 = warp_reduce_add(d3);

                    if (lane == 0) {
                        if (k < CAP)                 { scol[rr][k]     = jj0; sval[rr][k]     = d0; }
                        if (jj1 >= 0 && k + 1 < CAP) { scol[rr][k + 1] = jj1; sval[rr][k + 1] = d1; }
                        if (jj2 >= 0 && k + 2 < CAP) { scol[rr][k + 2] = jj2; sval[rr][k + 2] = d2; }
                        if (jj3 >= 0 && k + 3 < CAP) { scol[rr][k + 3] = jj3; sval[rr][k + 3] = d3; }
                    }
                    k += 1 + (jj1 >= 0) + (jj2 >= 0) + (jj3 >= 0);
                }
            }
        }
        if (lane == 0) {
            if (k > CAP) { scnt[rr] = CAP; sover[rr] = 1; }   // extremely unlikely
            else         { scnt[rr] = k; }
        }
    }
    __syncthreads();

    // --- wait for the zero-fill of our rows to be globally visible ---
    if (tid == 0) {
        asm volatile("cp.async.bulk.wait_group 0;" ::: "memory");
        asm volatile("fence.proxy.async;" ::: "memory");
    }
    __syncthreads();

    // --- scatter staged values into our (now zeroed) rows ---
    for (int idx = tid; idx < ROWS_PER_CTA * CAP; idx += 128) {
        const int r = idx / CAP, s = idx % CAP;
        if (s < scnt[r])
            out[(size_t)(row0 + r) * (size_t)N + (size_t)scol[r][s]] = sval[r][s];
    }

    // --- overflow slow path (never expected; correctness guarantee) ---
    for (int rr = w * 2; rr < w * 2 + 2; rr++) {
        if (!sover[rr]) continue;
        const int row = row0 + rr;
        const int ci = cls[row];
        const int bi = batch[row];
        const int lo = lower_bound_dev(batch, N, bi);
        const int hi = upper_bound_dev(batch, N, bi);
        const float4 a = reinterpret_cast<const float4*>(z1 + (size_t)row * 128)[lane];
        float* orow = out + (size_t)row * (size_t)N;
        for (int jb = lo; jb < hi; jb += 32) {
            const int j = jb + lane;
            const bool p = (j < hi) && (j != row) && (cls[j] == ci);
            unsigned m = __ballot_sync(0xffffffffu, p);
            while (m) {
                const int b = __ffs(m) - 1; m &= m - 1;
                const int jj = jb + b;
                const float4 v = reinterpret_cast<const float4*>(z2 + (size_t)jj * 128)[lane];
                float d = a.x * v.x + a.y * v.y + a.z * v.z + a.w * v.w;
                d = warp_reduce_add(d);
                if (lane == 0) orow[jj] = d;
            }
        }
    }
}

// ----------------- generic fallback (any shape): memset + direct -----------
__global__ void seg_decoder_sparse_generic(const float* __restrict__ z1,
                                           const float* __restrict__ z2,
                                           const int*  __restrict__ cls,
                                           const int*  __restrict__ batch,
                                           float* __restrict__ out,
                                           int N, int D)
{
    const int lane = threadIdx.x & 31;
    const int row  = (blockIdx.x * blockDim.x + threadIdx.x) >> 5;
    if (row >= N) return;

    const int ci = cls[row];
    if (ci >= 24 && ci <= 26) return;
    const int bi = batch[row];
    const int lo = lower_bound_dev(batch, N, bi);
    const int hi = upper_bound_dev(batch, N, bi);
    const float* arow = z1 + (size_t)row * D;
    float* orow = out + (size_t)row * (size_t)N;

    for (int jb = lo; jb < hi; jb += 32) {
        const int j = jb + lane;
        const bool p = (j < hi) && (j != row) && (cls[j] == ci);
        unsigned m = __ballot_sync(0xffffffffu, p);
        while (m) {
            const int b = __ffs(m) - 1; m &= m - 1;
            const int jj = jb + b;
            const float* vrow = z2 + (size_t)jj * D;
            float d = 0.f;
            for (int kk = lane; kk < D; kk += 32) d += arow[kk] * vrow[kk];
            d = warp_reduce_add(d);
            if (lane == 0) orow[jj] = d;
        }
    }
}

extern "C" void kernel_launch(void* const* d_in, const int* in_sizes, int n_in,
                              void* d_out, int out_size)
{
    const float* z1    = (const float*)d_in[0];
    const float* z2    = (const float*)d_in[1];
    const int*   cls   = (const int*)d_in[2];
    const int*   batch = (const int*)d_in[3];
    float*       out   = (float*)d_out;

    const int N = in_sizes[2];
    const int D = in_sizes[0] / N;

    const size_t rowBytes = (size_t)N * sizeof(float);
    if (D == 128 && (N % ROWS_PER_CTA) == 0 && (rowBytes % CHUNK) == 0) {
        const int chunksPerRow = (int)(rowBytes / CHUNK);
        const int ctas = N / ROWS_PER_CTA;
        fused_tma_fill_d128<<<ctas, 128>>>(z1, z2, cls, batch, out, N, chunksPerRow);
    } else {
        cudaMemsetAsync(out, 0, (size_t)out_size * sizeof(float));
        const int blocks = (N * 32 + 255) / 256;
        seg_decoder_sparse_generic<<<blocks, 256>>>(z1, z2, cls, batch, out, N, D);
    }
}

// round 8
// speedup vs baseline: 1.4133x; 1.4133x over previous
#include <cuda_runtime.h>
#include <cuda_bf16.h>

// out[i,j] = dot(z1[i], z2[j]) if batch[i]==batch[j] && cls[i]==cls[j]
//            && !(24<=cls[i]<=26) && i!=j, else 0.
//
// Single fused kernel, one warp per output row, no inter-warp sync:
//   phase 1: sparse dots for this row -> SMEM staging (L2 not yet trashed
//            by the fill; z2/cls/batch stay resident)
//   phase 2: zero-fill the row with a pure STG.128 stream (~7TB/s aggregate)
//   phase 3: overwrite the ~10 staged values (SMEM reads only)
// Phase order is the whole trick: gathers never run against the dirty-L2
// store stream (the failure mode of rounds 1/2/6).

#define CAP 64               // staged matches per row (avg ~9.5; tail-safe)

__device__ __forceinline__ int lower_bound_dev(const int* __restrict__ a, int n, int v) {
    int lo = 0, hi = n;
    while (lo < hi) { int m = (lo + hi) >> 1; if (a[m] < v) lo = m + 1; else hi = m; }
    return lo;
}
__device__ __forceinline__ int upper_bound_dev(const int* __restrict__ a, int n, int v) {
    int lo = 0, hi = n;
    while (lo < hi) { int m = (lo + hi) >> 1; if (a[m] <= v) lo = m + 1; else hi = m; }
    return lo;
}
__device__ __forceinline__ float warp_reduce_add(float d) {
    d += __shfl_xor_sync(0xffffffffu, d, 16);
    d += __shfl_xor_sync(0xffffffffu, d, 8);
    d += __shfl_xor_sync(0xffffffffu, d, 4);
    d += __shfl_xor_sync(0xffffffffu, d, 2);
    d += __shfl_xor_sync(0xffffffffu, d, 1);
    return d;
}

__global__ void __launch_bounds__(256)
fused_sparse_then_fill_d128(const float* __restrict__ z1,
                            const float* __restrict__ z2,
                            const int*  __restrict__ cls,
                            const int*  __restrict__ batch,
                            float* __restrict__ out,
                            int N)
{
    __shared__ int   scol[8][CAP];   // 8 warps per block
    __shared__ float sval[8][CAP];

    const int lane = threadIdx.x & 31;
    const int w    = threadIdx.x >> 5;
    const int row  = (blockIdx.x * blockDim.x + threadIdx.x) >> 5;
    if (row >= N) return;

    // ---------------- phase 1: sparse dots -> SMEM staging ----------------
    int k = 0;                         // uniform across the warp
    const int ci = cls[row];
    if (!(ci >= 24 && ci <= 26)) {
        const int bi = batch[row];
        const int lo = lower_bound_dev(batch, N, bi);
        const int hi = upper_bound_dev(batch, N, bi);
        const float4 a  = reinterpret_cast<const float4*>(z1 + (size_t)row * 128)[lane];
        const float4 zv = make_float4(0.f, 0.f, 0.f, 0.f);

        for (int jb = lo; jb < hi; jb += 32) {
            const int j = jb + lane;
            const bool p = (j < hi) && (j != row) && (cls[j] == ci);
            unsigned m = __ballot_sync(0xffffffffu, p);
            while (m) {
                // peel up to 4 matches -> 4 independent load/reduce chains
                int jj0 = jb + __ffs(m) - 1; m &= m - 1;
                int jj1 = -1, jj2 = -1, jj3 = -1;
                if (m) { jj1 = jb + __ffs(m) - 1; m &= m - 1; }
                if (m) { jj2 = jb + __ffs(m) - 1; m &= m - 1; }
                if (m) { jj3 = jb + __ffs(m) - 1; m &= m - 1; }

                float4 v0 = reinterpret_cast<const float4*>(z2 + (size_t)jj0 * 128)[lane];
                float4 v1 = (jj1 >= 0) ? reinterpret_cast<const float4*>(z2 + (size_t)jj1 * 128)[lane] : zv;
                float4 v2 = (jj2 >= 0) ? reinterpret_cast<const float4*>(z2 + (size_t)jj2 * 128)[lane] : zv;
                float4 v3 = (jj3 >= 0) ? reinterpret_cast<const float4*>(z2 + (size_t)jj3 * 128)[lane] : zv;

                float d0 = a.x * v0.x + a.y * v0.y + a.z * v0.z + a.w * v0.w;
                float d1 = a.x * v1.x + a.y * v1.y + a.z * v1.z + a.w * v1.w;
                float d2 = a.x * v2.x + a.y * v2.y + a.z * v2.z + a.w * v2.w;
                float d3 = a.x * v3.x + a.y * v3.y + a.z * v3.z + a.w * v3.w;

                d0 = warp_reduce_add(d0);
                d1 = warp_reduce_add(d1);
                d2 = warp_reduce_add(d2);
                d3 = warp_reduce_add(d3);

                if (lane == 0) {
                    if (k < CAP)                 { scol[w][k]     = jj0; sval[w][k]     = d0; }
                    if (jj1 >= 0 && k + 1 < CAP) { scol[w][k + 1] = jj1; sval[w][k + 1] = d1; }
                    if (jj2 >= 0 && k + 2 < CAP) { scol[w][k + 2] = jj2; sval[w][k + 2] = d2; }
                    if (jj3 >= 0 && k + 3 < CAP) { scol[w][k + 3] = jj3; sval[w][k + 3] = d3; }
                }
                k += 1 + (jj1 >= 0) + (jj2 >= 0) + (jj3 >= 0);
            }
        }
    }
    __syncwarp();   // staging visible warp-wide before/independent of fill

    // ---------------- phase 2: zero-fill this row (pure store stream) -----
    float4* orow4 = reinterpret_cast<float4*>(out + (size_t)row * (size_t)N);
    const int n4 = N >> 2;
    const float4 z = make_float4(0.f, 0.f, 0.f, 0.f);
    #pragma unroll 8
    for (int i = lane; i < n4; i += 32) orow4[i] = z;

    __syncwarp();   // order fill stores before value overwrites (cross-lane)

    // ---------------- phase 3: overwrite staged values (SMEM only) --------
    float* orow = out + (size_t)row * (size_t)N;
    const int kk = min(k, CAP);
    for (int s = lane; s < kk; s += 32)
        orow[scol[w][s]] = sval[w][s];

    // ---------------- overflow slow path (never expected) -----------------
    if (k > CAP) {
        const int bi = batch[row];
        const int lo = lower_bound_dev(batch, N, bi);
        const int hi = upper_bound_dev(batch, N, bi);
        const float4 a = reinterpret_cast<const float4*>(z1 + (size_t)row * 128)[lane];
        for (int jb = lo; jb < hi; jb += 32) {
            const int j = jb + lane;
            const bool p = (j < hi) && (j != row) && (cls[j] == ci);
            unsigned m = __ballot_sync(0xffffffffu, p);
            while (m) {
                const int b = __ffs(m) - 1; m &= m - 1;
                const int jj = jb + b;
                const float4 v = reinterpret_cast<const float4*>(z2 + (size_t)jj * 128)[lane];
                float d = a.x * v.x + a.y * v.y + a.z * v.z + a.w * v.w;
                d = warp_reduce_add(d);
                if (lane == 0) orow[jj] = d;
            }
        }
    }
}

// ----------------- generic fallback (any D): memset + direct scatter -------
__global__ void seg_decoder_sparse_generic(const float* __restrict__ z1,
                                           const float* __restrict__ z2,
                                           const int*  __restrict__ cls,
                                           const int*  __restrict__ batch,
                                           float* __restrict__ out,
                                           int N, int D)
{
    const int lane = threadIdx.x & 31;
    const int row  = (blockIdx.x * blockDim.x + threadIdx.x) >> 5;
    if (row >= N) return;

    const int ci = cls[row];
    if (ci >= 24 && ci <= 26) return;
    const int bi = batch[row];
    const int lo = lower_bound_dev(batch, N, bi);
    const int hi = upper_bound_dev(batch, N, bi);
    const float* arow = z1 + (size_t)row * D;
    float* orow = out + (size_t)row * (size_t)N;

    for (int jb = lo; jb < hi; jb += 32) {
        const int j = jb + lane;
        const bool p = (j < hi) && (j != row) && (cls[j] == ci);
        unsigned m = __ballot_sync(0xffffffffu, p);
        while (m) {
            const int b = __ffs(m) - 1; m &= m - 1;
            const int jj = jb + b;
            const float* vrow = z2 + (size_t)jj * D;
            float d = 0.f;
            for (int kk = lane; kk < D; kk += 32) d += arow[kk] * vrow[kk];
            d = warp_reduce_add(d);
            if (lane == 0) orow[jj] = d;
        }
    }
}

extern "C" void kernel_launch(void* const* d_in, const int* in_sizes, int n_in,
                              void* d_out, int out_size)
{
    const float* z1    = (const float*)d_in[0];
    const float* z2    = (const float*)d_in[1];
    const int*   cls   = (const int*)d_in[2];
    const int*   batch = (const int*)d_in[3];
    float*       out   = (float*)d_out;

    const int N = in_sizes[2];
    const int D = in_sizes[0] / N;

    if (D == 128 && (N & 3) == 0) {
        const int blocks = (N * 32 + 255) / 256;   // one warp per row
        fused_sparse_then_fill_d128<<<blocks, 256>>>(z1, z2, cls, batch, out, N);
    } else {
        cudaMemsetAsync(out, 0, (size_t)out_size * sizeof(float));
        const int blocks = (N * 32 + 255) / 256;
        seg_decoder_sparse_generic<<<blocks, 256>>>(z1, z2, cls, batch, out, N, D);
    }
}